// round 7
// baseline (speedup 1.0000x reference)
#include <cuda_runtime.h>

// DropBlock: x [64,256,64,64] f32, u [58,58] f32. BLOCK_SIZE=7, DROP_PROB=0.1
// k1 (128 thr, ballot bitboards, ~2us) --PDL--> k2 (streaming multiply).
// k2 front-loads x (mask-independent), then cudaGridDependencySynchronize()
// before reading d_mult.

#define H 64
#define W 64
#define HW 4096
#define US 58           // H - BS + 1
#define BS 7
#define DROP_PROB 0.1f

typedef unsigned long long u64;

__device__ __align__(16) float d_mult[HW];

// ---------------- Kernel 1: mask via warp ballots ----------------
__global__ void build_mask_kernel(const float* __restrict__ u) {
    cudaTriggerProgrammaticLaunchCompletion();

    __shared__ u64 s_hdil[US];
    __shared__ u64 s_vdil[H];
    __shared__ int s_sum;

    int tid  = threadIdx.x;       // 128 threads = 4 warps
    int lane = tid & 31;
    int warp = tid >> 5;
    if (tid == 0) s_sum = 0;

    // Each warp handles rows warp, warp+4, ... Bits built with ballots.
    for (int row = warp; row < US; row += 4) {
        const float* r = u + row * US;
        float v0 = r[lane];                                   // cols 0..31
        float v1 = (lane + 32 < US) ? r[lane + 32] : 1.0f;    // cols 32..57
        unsigned m0 = __ballot_sync(0xFFFFFFFFu, v0 < DROP_PROB);
        unsigned m1 = __ballot_sync(0xFFFFFFFFu, v1 < DROP_PROB);
        u64 b = (u64)m0 | ((u64)m1 << 32);
        u64 h = b;
        #pragma unroll
        for (int s = 1; s < BS; s++) h |= b << s;             // horiz dilation
        if (lane == 0) s_hdil[row] = h;
    }
    __syncthreads();

    // Vertical dilation + keep-count (threads 0..63 = 2 warps)
    if (tid < H) {
        int i0 = tid - (BS - 1); if (i0 < 0) i0 = 0;
        int i1 = tid;            if (i1 > US - 1) i1 = US - 1;
        u64 v = 0ULL;
        for (int i = i0; i <= i1; i++) v |= s_hdil[i];
        s_vdil[tid] = v;
        int keep = W - __popcll(v);
        #pragma unroll
        for (int off = 16; off > 0; off >>= 1)
            keep += __shfl_down_sync(0xFFFFFFFFu, keep, off);
        if (lane == 0) atomicAdd(&s_sum, keep);
    }
    __syncthreads();

    float scale = (float)HW / (float)s_sum;

    // Write table: thread t -> row t>>1, 32-col half (t&1), as 8 float4s.
    int y  = tid >> 1;
    int xh = (tid & 1) * 32;
    u64 v = s_vdil[y];
    float4* out = reinterpret_cast<float4*>(d_mult);
    #pragma unroll
    for (int q = 0; q < 8; q++) {
        int x = xh + q * 4;
        float4 f;
        f.x = ((v >> (x + 0)) & 1ULL) ? 0.0f : scale;
        f.y = ((v >> (x + 1)) & 1ULL) ? 0.0f : scale;
        f.z = ((v >> (x + 2)) & 1ULL) ? 0.0f : scale;
        f.w = ((v >> (x + 3)) & 1ULL) ? 0.0f : scale;
        out[(y * 64 + x) >> 2] = f;
    }
}

// ---------------- Kernel 2: streaming multiply (PDL consumer) ----------------
// Plain loads/stores (best measured BW: 6163 GB/s in R1).
__global__ void apply_mask_kernel(const float4* __restrict__ x4,
                                  float4* __restrict__ out4,
                                  int n4) {
    int idx = blockIdx.x * blockDim.x + threadIdx.x;
    bool valid = idx < n4;

    float4 v;
    if (valid) v = x4[idx];          // mask-independent: overlaps k1

    cudaGridDependencySynchronize(); // d_mult now visible

    if (!valid) return;
    const float4* m4 = reinterpret_cast<const float4*>(d_mult);
    float4 m = __ldg(&m4[idx & 1023]);
    v.x *= m.x; v.y *= m.y; v.z *= m.z; v.w *= m.w;
    out4[idx] = v;
}

extern "C" void kernel_launch(void* const* d_in, const int* in_sizes, int n_in,
                              void* d_out, int out_size) {
    const float* x = (const float*)d_in[0];
    const float* u = (const float*)d_in[1];
    float* out = (float*)d_out;

    build_mask_kernel<<<1, 128>>>(u);

    int n4 = out_size / 4;               // 16,777,216 float4s
    int threads = 256;
    int blocks = (n4 + threads - 1) / threads;

    cudaLaunchConfig_t cfg = {};
    cfg.gridDim = dim3(blocks, 1, 1);
    cfg.blockDim = dim3(threads, 1, 1);
    cfg.dynamicSmemBytes = 0;
    cfg.stream = 0;
    cudaLaunchAttribute attr[1];
    attr[0].id = cudaLaunchAttributeProgrammaticStreamSerialization;
    attr[0].val.programmaticStreamSerializationAllowed = 1;
    cfg.attrs = attr;
    cfg.numAttrs = 1;

    cudaLaunchKernelEx(&cfg, apply_mask_kernel,
                       (const float4*)x, (float4*)out, n4);
}

// round 8
// speedup vs baseline: 1.0863x; 1.0863x over previous
#include <cuda_runtime.h>

// DropBlock: x [64,256,64,64] f32, u [58,58] f32. BLOCK_SIZE=7, DROP_PROB=0.1
// k1 (1024 thr: ballot bitboards, all u-loads issued in parallel, ~1us)
//   --PDL--> k2 (streaming multiply, plain ld/st: best measured 6.2 TB/s).
// k2 front-loads x (mask-independent), then cudaGridDependencySynchronize()
// before reading d_mult.

#define H 64
#define W 64
#define HW 4096
#define US 58           // H - BS + 1
#define BS 7
#define DROP_PROB 0.1f

typedef unsigned long long u64;

__device__ __align__(16) float d_mult[HW];

// ---------------- Kernel 1: mask via warp ballots, max MLP ----------------
// 1024 threads = 32 warps. Warp w handles row w (w<32) and row w+32 (w<26):
// every u load is issued before any dependency -> one DRAM round-trip total.
__global__ __launch_bounds__(1024)
void build_mask_kernel(const float* __restrict__ u) {
    cudaTriggerProgrammaticLaunchCompletion();

    __shared__ u64 s_hdil[US];
    __shared__ u64 s_vdil[H];
    __shared__ int s_sum;

    int tid  = threadIdx.x;
    int lane = tid & 31;
    int warp = tid >> 5;
    if (tid == 0) s_sum = 0;

    // Row A = warp (always valid: 32 <= 58), Row B = warp + 32 (valid if < 58)
    int rowA = warp;
    int rowB = warp + 32;
    const float* rA = u + rowA * US;

    // Issue ALL loads up front (independent).
    float a0 = rA[lane];
    float a1 = (lane + 32 < US) ? rA[lane + 32] : 1.0f;
    float b0 = 1.0f, b1 = 1.0f;
    if (rowB < US) {
        const float* rB = u + rowB * US;
        b0 = rB[lane];
        b1 = (lane + 32 < US) ? rB[lane + 32] : 1.0f;
    }

    // Row A bits + horizontal dilation
    {
        unsigned m0 = __ballot_sync(0xFFFFFFFFu, a0 < DROP_PROB);
        unsigned m1 = __ballot_sync(0xFFFFFFFFu, a1 < DROP_PROB);
        u64 b = (u64)m0 | ((u64)m1 << 32);
        u64 h = b;
        #pragma unroll
        for (int s = 1; s < BS; s++) h |= b << s;
        if (lane == 0) s_hdil[rowA] = h;
    }
    // Row B bits + horizontal dilation
    {
        unsigned m0 = __ballot_sync(0xFFFFFFFFu, b0 < DROP_PROB);
        unsigned m1 = __ballot_sync(0xFFFFFFFFu, b1 < DROP_PROB);
        if (rowB < US) {
            u64 b = (u64)m0 | ((u64)m1 << 32);
            u64 h = b;
            #pragma unroll
            for (int s = 1; s < BS; s++) h |= b << s;
            if (lane == 0) s_hdil[rowB] = h;
        }
    }
    __syncthreads();

    // Vertical dilation + keep count (threads 0..63)
    if (tid < H) {
        int i0 = tid - (BS - 1); if (i0 < 0) i0 = 0;
        int i1 = tid;            if (i1 > US - 1) i1 = US - 1;
        u64 v = 0ULL;
        for (int i = i0; i <= i1; i++) v |= s_hdil[i];
        s_vdil[tid] = v;
        int keep = W - __popcll(v);
        #pragma unroll
        for (int off = 16; off > 0; off >>= 1)
            keep += __shfl_down_sync(0xFFFFFFFFu, keep, off);
        if (lane == 0) atomicAdd(&s_sum, keep);
    }
    __syncthreads();

    float scale = (float)HW / (float)s_sum;

    // Write table: 1024 float4s, one per thread (4096 floats total).
    int q = tid;                 // float4 index 0..1023
    int y = q >> 4;              // 16 float4s per row
    int x = (q & 15) * 4;
    u64 v = s_vdil[y];
    float4 f;
    f.x = ((v >> (x + 0)) & 1ULL) ? 0.0f : scale;
    f.y = ((v >> (x + 1)) & 1ULL) ? 0.0f : scale;
    f.z = ((v >> (x + 2)) & 1ULL) ? 0.0f : scale;
    f.w = ((v >> (x + 3)) & 1ULL) ? 0.0f : scale;
    reinterpret_cast<float4*>(d_mult)[q] = f;
}

// ---------------- Kernel 2: streaming multiply (PDL consumer) ----------------
__global__ void apply_mask_kernel(const float4* __restrict__ x4,
                                  float4* __restrict__ out4,
                                  int n4) {
    int idx = blockIdx.x * blockDim.x + threadIdx.x;
    bool valid = idx < n4;

    float4 v;
    if (valid) v = x4[idx];          // mask-independent: overlaps k1

    cudaGridDependencySynchronize(); // d_mult now visible

    if (!valid) return;
    const float4* m4 = reinterpret_cast<const float4*>(d_mult);
    float4 m = __ldg(&m4[idx & 1023]);
    v.x *= m.x; v.y *= m.y; v.z *= m.z; v.w *= m.w;
    out4[idx] = v;
}

extern "C" void kernel_launch(void* const* d_in, const int* in_sizes, int n_in,
                              void* d_out, int out_size) {
    const float* x = (const float*)d_in[0];
    const float* u = (const float*)d_in[1];
    float* out = (float*)d_out;

    build_mask_kernel<<<1, 1024>>>(u);

    int n4 = out_size / 4;               // 16,777,216 float4s
    int threads = 256;
    int blocks = (n4 + threads - 1) / threads;

    cudaLaunchConfig_t cfg = {};
    cfg.gridDim = dim3(blocks, 1, 1);
    cfg.blockDim = dim3(threads, 1, 1);
    cfg.dynamicSmemBytes = 0;
    cfg.stream = 0;
    cudaLaunchAttribute attr[1];
    attr[0].id = cudaLaunchAttributeProgrammaticStreamSerialization;
    attr[0].val.programmaticStreamSerializationAllowed = 1;
    cfg.attrs = attr;
    cfg.numAttrs = 1;

    cudaLaunchKernelEx(&cfg, apply_mask_kernel,
                       (const float4*)x, (float4*)out, n4);
}